// round 9
// baseline (speedup 1.0000x reference)
#include <cuda_runtime.h>
#include <cuda_fp16.h>
#include <math.h>
#include <stdint.h>

#define N_SITES 100000
#define DIM 128
#define HID 512
#define KVOL 343

// ---------------- scratch (device globals; no runtime allocation) ----------
__device__ __align__(16) __half g_x[N_SITES * DIM];            // LN output
__device__ __align__(16) __half g_h[(size_t)N_SITES * HID];    // GELU output
__device__ __align__(16) __half g_w1t[HID * DIM];              // w1 transposed [n][k]
__device__ __align__(16) __half g_w2s[DIM * HID];              // scaled w2 [n][k]
__device__ float g_sumsq[HID];
__device__ float g_bias2[DIM];

// ---------------- PTX helpers ----------------------------------------------
__device__ __forceinline__ uint32_t smem_u32(const void* p) {
  uint32_t a;
  asm("{ .reg .u64 t; cvta.to.shared.u64 t, %1; cvt.u32.u64 %0, t; }"
      : "=r"(a) : "l"(p));
  return a;
}

__device__ __forceinline__ void cpa16(uint32_t dst, const void* src, uint32_t sz) {
  asm volatile("cp.async.cg.shared.global [%0], [%1], 16, %2;"
               ::"r"(dst), "l"(src), "r"(sz) : "memory");
}
#define CP_COMMIT() asm volatile("cp.async.commit_group;" ::: "memory")
#define CP_WAIT1() asm volatile("cp.async.wait_group 1;" ::: "memory")
#define CP_WAIT0() asm volatile("cp.async.wait_group 0;" ::: "memory")

__device__ __forceinline__ void ldsm4(uint32_t* r, uint32_t addr) {
  asm volatile("ldmatrix.sync.aligned.m8n8.x4.shared.b16 {%0,%1,%2,%3}, [%4];"
               : "=r"(r[0]), "=r"(r[1]), "=r"(r[2]), "=r"(r[3]) : "r"(addr));
}

__device__ __forceinline__ void stsm4(uint32_t addr, uint32_t r0, uint32_t r1,
                                      uint32_t r2, uint32_t r3) {
  asm volatile("stmatrix.sync.aligned.m8n8.x4.shared.b16 [%0], {%1,%2,%3,%4};"
               ::"r"(addr), "r"(r0), "r"(r1), "r"(r2), "r"(r3) : "memory");
}

__device__ __forceinline__ void mma16816(float* d, const uint32_t* a, const uint32_t* b) {
  asm volatile(
      "mma.sync.aligned.m16n8k16.row.col.f32.f16.f16.f32 "
      "{%0,%1,%2,%3}, {%4,%5,%6,%7}, {%8,%9}, {%0,%1,%2,%3};"
      : "+f"(d[0]), "+f"(d[1]), "+f"(d[2]), "+f"(d[3])
      : "r"(a[0]), "r"(a[1]), "r"(a[2]), "r"(a[3]), "r"(b[0]), "r"(b[1]));
}

// ---------------- tiling ----------------------------------------------------
#define STG_HB 272       // fp16 epilogue stage row bytes (gemm1): 136 halfs
#define G1_OFF_B 32768
#define G1_OFF_STG 65536
#define G1_SMEM 100352   // A 32K + B 32K + stage 34816
#define G2_STAGE 32768
#define G2_OFF_B 16384
#define G2_SMEM 98304

// ---------------------------------------------------------------------------
// Kernel 1: sparse depthwise conv + LayerNorm -> fp16
// One warp per site; float4 per lane; warp-local compaction + LN reduce.
// ---------------------------------------------------------------------------
__global__ __launch_bounds__(256) void k_dwln(
    const float* __restrict__ feats, const int* __restrict__ nidx,
    const float* __restrict__ dw_w, const float* __restrict__ dw_b,
    const float* __restrict__ ln_g, const float* __restrict__ ln_b) {
  int wrp = threadIdx.x >> 5, lane = threadIdx.x & 31;
  int site = blockIdx.x * 8 + wrp;  // 12500 * 8 = 100000 exactly
  __shared__ int s_k[8][344];
  __shared__ int s_i[8][344];
  const int* row = nidx + (size_t)site * KVOL;

  int base = 0;
#pragma unroll
  for (int it = 0; it < 11; it++) {
    int k = it * 32 + lane;
    int idx = (k < KVOL) ? row[k] : N_SITES;
    bool valid = idx < N_SITES;
    uint32_t m = __ballot_sync(0xffffffffu, valid);
    if (valid) {
      int pos = base + __popc(m & ((1u << lane) - 1u));
      s_k[wrp][pos] = k;
      s_i[wrp][pos] = idx;
    }
    base += __popc(m);
  }
  int cnt = base;
  __syncwarp();

  const float4* f4 = (const float4*)feats;
  const float4* w4 = (const float4*)dw_w;
  float4 bb = ((const float4*)dw_b)[lane];
  float a0 = bb.x, a1 = bb.y, a2 = bb.z, a3 = bb.w;
  int v = 0;
  for (; v + 2 <= cnt; v += 2) {
    int ka = s_k[wrp][v], ia = s_i[wrp][v];
    int kb = s_k[wrp][v + 1], ib = s_i[wrp][v + 1];
    float4 fa = __ldg(&f4[(size_t)ia * 32 + lane]);
    float4 wa = __ldg(&w4[(size_t)ka * 32 + lane]);
    float4 fb = __ldg(&f4[(size_t)ib * 32 + lane]);
    float4 wb = __ldg(&w4[(size_t)kb * 32 + lane]);
    a0 += fa.x * wa.x + fb.x * wb.x;
    a1 += fa.y * wa.y + fb.y * wb.y;
    a2 += fa.z * wa.z + fb.z * wb.z;
    a3 += fa.w * wa.w + fb.w * wb.w;
  }
  if (v < cnt) {
    int ka = s_k[wrp][v], ia = s_i[wrp][v];
    float4 fa = __ldg(&f4[(size_t)ia * 32 + lane]);
    float4 wa = __ldg(&w4[(size_t)ka * 32 + lane]);
    a0 += fa.x * wa.x;
    a1 += fa.y * wa.y;
    a2 += fa.z * wa.z;
    a3 += fa.w * wa.w;
  }

  float s1 = a0 + a1 + a2 + a3;
  float s2 = a0 * a0 + a1 * a1 + a2 * a2 + a3 * a3;
#pragma unroll
  for (int o = 16; o > 0; o >>= 1) {
    s1 += __shfl_xor_sync(0xffffffffu, s1, o);
    s2 += __shfl_xor_sync(0xffffffffu, s2, o);
  }
  float mu = s1 * (1.f / 128.f);
  float var = s2 * (1.f / 128.f) - mu * mu;
  float rstd = rsqrtf(var + 1e-6f);
  float4 gg = ((const float4*)ln_g)[lane];
  float4 gb = ((const float4*)ln_b)[lane];
  float v0 = (a0 - mu) * rstd * gg.x + gb.x;
  float v1 = (a1 - mu) * rstd * gg.y + gb.y;
  float v2 = (a2 - mu) * rstd * gg.z + gb.z;
  float v3 = (a3 - mu) * rstd * gg.w + gb.w;
  union { __half2 h[2]; uint2 u; } o;
  o.h[0] = __floats2half2_rn(v0, v1);
  o.h[1] = __floats2half2_rn(v2, v3);
  *(uint2*)&g_x[(size_t)site * DIM + lane * 4] = o.u;
}

// w1 [128,512] -> transposed fp16 w1t [n][k]; block 0 zeros g_sumsq
__global__ __launch_bounds__(256) void k_prepw1(const float* __restrict__ w1) {
  if (blockIdx.x == 0) {
    g_sumsq[threadIdx.x] = 0.f;
    g_sumsq[threadIdx.x + 256] = 0.f;
  }
  int i = blockIdx.x * 256 + threadIdx.x;  // 0..65535
  int n = i >> 7, k = i & 127;
  g_w1t[i] = __float2half_rn(w1[k * HID + n]);
}

// ---------------------------------------------------------------------------
// GEMM1: h = GELU(x @ w1 + b1)  (+ per-channel sumsq for GRN)
// N-persistent: one CTA per M-tile; A loaded once; loop 4 N-chunks of w1t.
// smem: A 32K | B 32K (single buffer, prefetch overlaps epilogue) | stage 34K.
// ---------------------------------------------------------------------------
__global__ __launch_bounds__(256, 2) void k_gemm1(const float* __restrict__ b1) {
  extern __shared__ char smem[];
  __shared__ float s_ss[HID];
  uint32_t sb = smem_u32(smem);
  int tid = threadIdx.x, lane = tid & 31, w = tid >> 5;
  int wm = w & 1, wn = w >> 1;
  int m0 = blockIdx.x * 128;
  for (int i = tid; i < HID; i += 256) s_ss[i] = 0.f;

  // ---- prologue: load A tile (x[m0..]) + B chunk 0 (w1t rows 0..127) ----
#pragma unroll
  for (int i = 0; i < 8; i++) {
    int g = i * 256 + tid;
    int r = g >> 4, c16 = g & 15;
    uint32_t sw = ((uint32_t)(c16 >> 3) << 14) + r * 128 + (((c16 & 7) ^ (r & 7)) << 4);
    int gr = m0 + r;
    uint32_t sz = (gr < N_SITES) ? 16u : 0u;
    int grc = (gr < N_SITES) ? gr : 0;
    cpa16(sb + sw, g_x + (size_t)grc * DIM + c16 * 8, sz);
    cpa16(sb + G1_OFF_B + sw, g_w1t + (size_t)r * DIM + c16 * 8, 16);
  }
  CP_COMMIT();

  // ---- ldsm offset precompute ----
  uint32_t abase[4], axor[4], bbase[2], bxor[2];
  {
    int ar = wm * 64 + (lane & 15);
#pragma unroll
    for (int mt = 0; mt < 4; mt++) {
      int r = ar + mt * 16;
      abase[mt] = r * 128;
      axor[mt] = (r & 7) << 4;
    }
    int br = wn * 32 + ((lane >> 4) << 3) + (lane & 7);
#pragma unroll
    for (int np = 0; np < 2; np++) {
      int r = br + np * 16;
      bbase[np] = G1_OFF_B + r * 128;
      bxor[np] = (r & 7) << 4;
    }
  }
  uint32_t acs = lane >> 4, bcs = (lane >> 3) & 1;
  uint32_t st_base = sb + G1_OFF_STG + (uint32_t)(wm * 64 + (lane & 7)) * STG_HB +
                     (uint32_t)(wn * 32 + ((lane >> 3) << 3)) * 2;

#pragma unroll 1
  for (int nc = 0; nc < 4; nc++) {
    int n0 = nc * 128;
    CP_WAIT0();
    __syncthreads();  // B chunk ready; prior copy-out complete

    float acc[4][4][4] = {};
#pragma unroll
    for (int ks = 0; ks < 8; ks++) {
      uint32_t ho = (uint32_t)(ks >> 2) << 14;
      uint32_t ksl = ks & 3;
      uint32_t a[4][4], b[2][4];
#pragma unroll
      for (int np = 0; np < 2; np++)
        ldsm4(b[np], sb + bbase[np] + ho + ((((ksl * 2 + bcs) << 4)) ^ bxor[np]));
#pragma unroll
      for (int mt = 0; mt < 4; mt++)
        ldsm4(a[mt], sb + abase[mt] + ho + ((((ksl * 2 + acs) << 4)) ^ axor[mt]));
#pragma unroll
      for (int mt = 0; mt < 4; mt++)
#pragma unroll
        for (int nt = 0; nt < 4; nt++)
          mma16816(acc[mt][nt], a[mt], &b[nt >> 1][(nt & 1) * 2]);
    }
    __syncthreads();  // all warps done reading B chunk

    // prefetch next B chunk into same buffer (overlaps epilogue)
    if (nc < 3) {
#pragma unroll
      for (int i = 0; i < 8; i++) {
        int g = i * 256 + tid;
        int r = g >> 4, c16 = g & 15;
        uint32_t sw = ((uint32_t)(c16 >> 3) << 14) + r * 128 + (((c16 & 7) ^ (r & 7)) << 4);
        cpa16(sb + G1_OFF_B + sw, g_w1t + (size_t)(n0 + 128 + r) * DIM + c16 * 8, 16);
      }
    }
    CP_COMMIT();

    // ---- fragment-space epilogue: bias + GELU + sumsq, stmatrix stage ----
    float2 b_r[4];
#pragma unroll
    for (int nt = 0; nt < 4; nt++)
      b_r[nt] = *(const float2*)&b1[n0 + wn * 32 + nt * 8 + (lane & 3) * 2];

    float ss[8] = {0, 0, 0, 0, 0, 0, 0, 0};
#pragma unroll
    for (int mt = 0; mt < 4; mt++) {
      int r0 = m0 + wm * 64 + mt * 16 + (lane >> 2);
      float ok0 = (r0 < N_SITES) ? 1.f : 0.f;
      float ok1 = (r0 + 8 < N_SITES) ? 1.f : 0.f;
      uint32_t p01[4], p23[4];
#pragma unroll
      for (int nt = 0; nt < 4; nt++) {
        float x0 = acc[mt][nt][0] + b_r[nt].x;
        float x1 = acc[mt][nt][1] + b_r[nt].y;
        float x2 = acc[mt][nt][2] + b_r[nt].x;
        float x3 = acc[mt][nt][3] + b_r[nt].y;
        float g0 = ok0 * 0.5f * x0 * (1.f + erff(x0 * 0.70710678118654752f));
        float g1 = ok0 * 0.5f * x1 * (1.f + erff(x1 * 0.70710678118654752f));
        float g2 = ok1 * 0.5f * x2 * (1.f + erff(x2 * 0.70710678118654752f));
        float g3 = ok1 * 0.5f * x3 * (1.f + erff(x3 * 0.70710678118654752f));
        ss[nt * 2] += g0 * g0 + g2 * g2;
        ss[nt * 2 + 1] += g1 * g1 + g3 * g3;
        union { __half2 h; uint32_t u; } u01, u23;
        u01.h = __floats2half2_rn(g0, g1);
        u23.h = __floats2half2_rn(g2, g3);
        p01[nt] = u01.u;
        p23[nt] = u23.u;
      }
      uint32_t a0 = st_base + (uint32_t)(mt * 16) * STG_HB;
      stsm4(a0, p01[0], p01[1], p01[2], p01[3]);
      stsm4(a0 + 8 * STG_HB, p23[0], p23[1], p23[2], p23[3]);
    }
#pragma unroll
    for (int e = 0; e < 8; e++) {
      ss[e] += __shfl_xor_sync(0xffffffffu, ss[e], 4);
      ss[e] += __shfl_xor_sync(0xffffffffu, ss[e], 8);
      ss[e] += __shfl_xor_sync(0xffffffffu, ss[e], 16);
    }
    if (lane < 4) {
#pragma unroll
      for (int nt = 0; nt < 4; nt++) {
        atomicAdd(&s_ss[n0 + wn * 32 + nt * 8 + (lane & 3) * 2], ss[nt * 2]);
        atomicAdd(&s_ss[n0 + wn * 32 + nt * 8 + (lane & 3) * 2 + 1], ss[nt * 2 + 1]);
      }
    }
    __syncthreads();  // stage complete before copy-out

    uint32_t ci = (tid & 15) * 16;
#pragma unroll
    for (int p = 0; p < 8; p++) {
      int rr = p * 16 + (tid >> 4);
      int m = m0 + rr;
      if (m < N_SITES) {
        uint4 v = *(uint4*)(smem + G1_OFF_STG + rr * STG_HB + ci);
        *(uint4*)&g_h[(size_t)m * HID + n0 + (tid & 15) * 8] = v;
      }
    }
  }
  __syncthreads();
  for (int i = tid; i < HID; i += 256) atomicAdd(&g_sumsq[i], s_ss[i]);
}

// ---------------------------------------------------------------------------
// Fold (with inline GRN): scale[k] = grn_g[k]*nx[k]+1;
// w2s[n][k] = scale[k]*w2[k][n]; bias2[n] = b2[n] + grn_b @ w2
// ---------------------------------------------------------------------------
__global__ __launch_bounds__(128) void k_fold(const float* __restrict__ grn_g,
                                              const float* __restrict__ grn_b,
                                              const float* __restrict__ w2,
                                              const float* __restrict__ b2) {
  int n = blockIdx.x;
  int t = threadIdx.x;
  float gx[4];
  float loc = 0.f;
#pragma unroll
  for (int j = 0; j < 4; j++) {
    gx[j] = sqrtf(g_sumsq[t + j * 128]);
    loc += gx[j];
  }
  __shared__ float red[4];
#pragma unroll
  for (int o = 16; o > 0; o >>= 1) loc += __shfl_xor_sync(0xffffffffu, loc, o);
  if ((t & 31) == 0) red[t >> 5] = loc;
  __syncthreads();
  float mean = (red[0] + red[1] + red[2] + red[3]) * (1.f / 512.f);
  float inv = 1.f / (mean + 1e-6f);

  float part = 0.f;
#pragma unroll
  for (int j = 0; j < 4; j++) {
    int kk = t + j * 128;
    float wv = w2[kk * DIM + n];
    part += grn_b[kk] * wv;
    float scale = grn_g[kk] * (gx[j] * inv) + 1.f;
    g_w2s[n * HID + kk] = __float2half_rn(scale * wv);
  }
#pragma unroll
  for (int o = 16; o > 0; o >>= 1) part += __shfl_xor_sync(0xffffffffu, part, o);
  if ((t & 31) == 0) red[t >> 5] = part;
  __syncthreads();
  if (t == 0) g_bias2[n] = b2[n] + red[0] + red[1] + red[2] + red[3];
}

// ---------------------------------------------------------------------------
// GEMM2: out = (h .* scale) @ w2 + bias2 + feats
// K=512 in 8 chunks of 64, 3-stage cp.async pipeline; fragment-direct epilogue.
// ---------------------------------------------------------------------------
__global__ __launch_bounds__(256, 2) void k_gemm2(const float* __restrict__ feats,
                                                  float* __restrict__ out) {
  extern __shared__ char smem[];
  uint32_t sb = smem_u32(smem);
  int tid = threadIdx.x, lane = tid & 31, w = tid >> 5;
  int wm = w & 1, wn = w >> 1;
  int m0 = blockIdx.x * 128;

  uint32_t abase[4], axor[4], bbase[2], bxor[2];
  {
    int ar = wm * 64 + (lane & 15);
#pragma unroll
    for (int mt = 0; mt < 4; mt++) {
      int r = ar + mt * 16;
      abase[mt] = r * 128;
      axor[mt] = (r & 7) << 4;
    }
    int br = wn * 32 + ((lane >> 4) << 3) + (lane & 7);
#pragma unroll
    for (int np = 0; np < 2; np++) {
      int r = br + np * 16;
      bbase[np] = G2_OFF_B + r * 128;
      bxor[np] = (r & 7) << 4;
    }
  }
  uint32_t acs = lane >> 4, bcs = (lane >> 3) & 1;

  int lr = tid >> 3, lc = tid & 7;

  float acc[4][4][4] = {};
  const int CH = HID / 64;  // 8

#pragma unroll
  for (int c = 0; c < 2; c++) {
    uint32_t ssb = sb + c * G2_STAGE;
    int k0 = c * 64;
#pragma unroll
    for (int i = 0; i < 4; i++) {
      int r = lr + i * 32;
      int gr = m0 + r;
      uint32_t sz = (gr < N_SITES) ? 16u : 0u;
      int grc = (gr < N_SITES) ? gr : 0;
      cpa16(ssb + r * 128 + (((lc ^ (r & 7))) << 4), g_h + (size_t)grc * HID + k0 + lc * 8, sz);
      cpa16(ssb + G2_OFF_B + r * 128 + (((lc ^ (r & 7))) << 4),
            g_w2s + (size_t)r * HID + k0 + lc * 8, 16);
    }
    CP_COMMIT();
  }
#pragma unroll 1
  for (int c = 0; c < CH; c++) {
    CP_WAIT1();
    __syncthreads();
    uint32_t ssb = sb + (c % 3) * G2_STAGE;
#pragma unroll
    for (int ks = 0; ks < 4; ks++) {
      uint32_t a[4][4], b[2][4];
#pragma unroll
      for (int np = 0; np < 2; np++)
        ldsm4(b[np], ssb + bbase[np] + ((((ks * 2 + bcs) << 4)) ^ bxor[np]));
#pragma unroll
      for (int mt = 0; mt < 4; mt++)
        ldsm4(a[mt], ssb + abase[mt] + ((((ks * 2 + acs) << 4)) ^ axor[mt]));
#pragma unroll
      for (int mt = 0; mt < 4; mt++)
#pragma unroll
        for (int nt = 0; nt < 4; nt++)
          mma16816(acc[mt][nt], a[mt], &b[nt >> 1][(nt & 1) * 2]);
    }
    int pc = c + 2;
    if (pc < CH) {
      uint32_t psb = sb + (pc % 3) * G2_STAGE;
      int k0 = pc * 64;
#pragma unroll
      for (int i = 0; i < 4; i++) {
        int r = lr + i * 32;
        int gr = m0 + r;
        uint32_t sz = (gr < N_SITES) ? 16u : 0u;
        int grc = (gr < N_SITES) ? gr : 0;
        cpa16(psb + r * 128 + (((lc ^ (r & 7))) << 4), g_h + (size_t)grc * HID + k0 + lc * 8, sz);
        cpa16(psb + G2_OFF_B + r * 128 + (((lc ^ (r & 7))) << 4),
              g_w2s + (size_t)r * HID + k0 + lc * 8, 16);
      }
    }
    CP_COMMIT();
  }

  // ---- fragment-direct epilogue: + bias2 + feats, float2 stores ----
  float2 b_r[4];
#pragma unroll
  for (int nt = 0; nt < 4; nt++)
    b_r[nt] = *(const float2*)&g_bias2[wn * 32 + nt * 8 + (lane & 3) * 2];
#pragma unroll
  for (int mt = 0; mt < 4; mt++) {
    int r0 = m0 + wm * 64 + mt * 16 + (lane >> 2);
#pragma unroll
    for (int nt = 0; nt < 4; nt++) {
      int n = wn * 32 + nt * 8 + (lane & 3) * 2;
      if (r0 < N_SITES) {
        float2 f = *(const float2*)&feats[(size_t)r0 * DIM + n];
        float2 o;
        o.x = acc[mt][nt][0] + b_r[nt].x + f.x;
        o.y = acc[mt][nt][1] + b_r[nt].y + f.y;
        *(float2*)&out[(size_t)r0 * DIM + n] = o;
      }
      if (r0 + 8 < N_SITES) {
        float2 f = *(const float2*)&feats[(size_t)(r0 + 8) * DIM + n];
        float2 o;
        o.x = acc[mt][nt][2] + b_r[nt].x + f.x;
        o.y = acc[mt][nt][3] + b_r[nt].y + f.y;
        *(float2*)&out[(size_t)(r0 + 8) * DIM + n] = o;
      }
    }
  }
}

// ---------------------------------------------------------------------------
extern "C" void kernel_launch(void* const* d_in, const int* in_sizes, int n_in,
                              void* d_out, int out_size) {
  const float* feats = (const float*)d_in[0];
  const int* nidx = (const int*)d_in[1];
  const float* dw_w = (const float*)d_in[2];
  const float* dw_b = (const float*)d_in[3];
  const float* ln_g = (const float*)d_in[4];
  const float* ln_b = (const float*)d_in[5];
  const float* w1 = (const float*)d_in[6];
  const float* b1 = (const float*)d_in[7];
  const float* grn_g = (const float*)d_in[8];
  const float* grn_b = (const float*)d_in[9];
  const float* w2 = (const float*)d_in[10];
  const float* b2 = (const float*)d_in[11];
  float* out = (float*)d_out;

  cudaFuncSetAttribute(k_gemm1, cudaFuncAttributeMaxDynamicSharedMemorySize, G1_SMEM);
  cudaFuncSetAttribute(k_gemm2, cudaFuncAttributeMaxDynamicSharedMemorySize, G2_SMEM);

  const int MT = (N_SITES + 127) / 128;  // 782
  k_prepw1<<<256, 256>>>(w1);
  k_dwln<<<N_SITES / 8, 256>>>(feats, nidx, dw_w, dw_b, ln_g, ln_b);
  k_gemm1<<<MT, 256, G1_SMEM>>>(b1);
  k_fold<<<DIM, 128>>>(grn_g, grn_b, w2, b2);
  k_gemm2<<<MT, 256, G2_SMEM>>>(feats, out);
}

// round 10
// speedup vs baseline: 1.1737x; 1.1737x over previous
#include <cuda_runtime.h>
#include <cuda_fp16.h>
#include <math.h>
#include <stdint.h>

#define N_SITES 100000
#define DIM 128
#define HID 512
#define KVOL 343

// ---------------- scratch (device globals; no runtime allocation) ----------
__device__ __align__(16) __half g_x[N_SITES * DIM];            // LN output
__device__ __align__(16) __half g_h[(size_t)N_SITES * HID];    // GELU output
__device__ __align__(16) __half g_w1t[HID * DIM];              // w1 transposed [n][k]
__device__ __align__(16) __half g_w2s[DIM * HID];              // scaled w2 [n][k]
__device__ float g_sumsq[HID];
__device__ float g_bias2[DIM];

// ---------------- PTX helpers ----------------------------------------------
__device__ __forceinline__ uint32_t smem_u32(const void* p) {
  uint32_t a;
  asm("{ .reg .u64 t; cvta.to.shared.u64 t, %1; cvt.u32.u64 %0, t; }"
      : "=r"(a) : "l"(p));
  return a;
}

__device__ __forceinline__ void cpa16(uint32_t dst, const void* src, uint32_t sz) {
  asm volatile("cp.async.cg.shared.global [%0], [%1], 16, %2;"
               ::"r"(dst), "l"(src), "r"(sz) : "memory");
}
#define CP_COMMIT() asm volatile("cp.async.commit_group;" ::: "memory")
#define CP_WAIT1() asm volatile("cp.async.wait_group 1;" ::: "memory")
#define CP_WAIT0() asm volatile("cp.async.wait_group 0;" ::: "memory")

__device__ __forceinline__ void ldsm4(uint32_t* r, uint32_t addr) {
  asm volatile("ldmatrix.sync.aligned.m8n8.x4.shared.b16 {%0,%1,%2,%3}, [%4];"
               : "=r"(r[0]), "=r"(r[1]), "=r"(r[2]), "=r"(r[3]) : "r"(addr));
}

__device__ __forceinline__ void stsm4(uint32_t addr, uint32_t r0, uint32_t r1,
                                      uint32_t r2, uint32_t r3) {
  asm volatile("stmatrix.sync.aligned.m8n8.x4.shared.b16 [%0], {%1,%2,%3,%4};"
               ::"r"(addr), "r"(r0), "r"(r1), "r"(r2), "r"(r3) : "memory");
}

__device__ __forceinline__ void mma16816(float* d, const uint32_t* a, const uint32_t* b) {
  asm volatile(
      "mma.sync.aligned.m16n8k16.row.col.f32.f16.f16.f32 "
      "{%0,%1,%2,%3}, {%4,%5,%6,%7}, {%8,%9}, {%0,%1,%2,%3};"
      : "+f"(d[0]), "+f"(d[1]), "+f"(d[2]), "+f"(d[3])
      : "r"(a[0]), "r"(a[1]), "r"(a[2]), "r"(a[3]), "r"(b[0]), "r"(b[1]));
}

// fast GELU: tanh form with HW tanh.approx (abs err ~5e-4, < fp16 quant noise)
__device__ __forceinline__ float gelu_fast(float x) {
  float u = x * (0.7978845608028654f + 0.035677408136300125f * x * x);
  float t;
  asm("tanh.approx.f32 %0, %1;" : "=f"(t) : "f"(u));
  return 0.5f * x * (1.f + t);
}

// ---------------- tiling ----------------------------------------------------
#define STG_HB 272       // fp16 epilogue stage row bytes (gemm1): 136 halfs
#define G1_OFF_B 32768
#define G1_SMEM 67584
#define G2_STAGE 32768
#define G2_OFF_B 16384
#define G2_SMEM 98304

// ---------------------------------------------------------------------------
// Kernel 1: sparse depthwise conv + LayerNorm -> fp16
// One warp per site; float4 per lane; warp-local compaction + LN reduce.
// ---------------------------------------------------------------------------
__global__ __launch_bounds__(256) void k_dwln(
    const float* __restrict__ feats, const int* __restrict__ nidx,
    const float* __restrict__ dw_w, const float* __restrict__ dw_b,
    const float* __restrict__ ln_g, const float* __restrict__ ln_b) {
  int wrp = threadIdx.x >> 5, lane = threadIdx.x & 31;
  int site = blockIdx.x * 8 + wrp;  // 12500 * 8 = 100000 exactly
  __shared__ int s_k[8][344];
  __shared__ int s_i[8][344];
  const int* row = nidx + (size_t)site * KVOL;

  int base = 0;
#pragma unroll
  for (int it = 0; it < 11; it++) {
    int k = it * 32 + lane;
    int idx = (k < KVOL) ? row[k] : N_SITES;
    bool valid = idx < N_SITES;
    uint32_t m = __ballot_sync(0xffffffffu, valid);
    if (valid) {
      int pos = base + __popc(m & ((1u << lane) - 1u));
      s_k[wrp][pos] = k;
      s_i[wrp][pos] = idx;
    }
    base += __popc(m);
  }
  int cnt = base;
  __syncwarp();

  const float4* f4 = (const float4*)feats;
  const float4* w4 = (const float4*)dw_w;
  float4 bb = ((const float4*)dw_b)[lane];
  float a0 = bb.x, a1 = bb.y, a2 = bb.z, a3 = bb.w;
  int v = 0;
  for (; v + 2 <= cnt; v += 2) {
    int ka = s_k[wrp][v], ia = s_i[wrp][v];
    int kb = s_k[wrp][v + 1], ib = s_i[wrp][v + 1];
    float4 fa = __ldg(&f4[(size_t)ia * 32 + lane]);
    float4 wa = __ldg(&w4[(size_t)ka * 32 + lane]);
    float4 fb = __ldg(&f4[(size_t)ib * 32 + lane]);
    float4 wb = __ldg(&w4[(size_t)kb * 32 + lane]);
    a0 += fa.x * wa.x + fb.x * wb.x;
    a1 += fa.y * wa.y + fb.y * wb.y;
    a2 += fa.z * wa.z + fb.z * wb.z;
    a3 += fa.w * wa.w + fb.w * wb.w;
  }
  if (v < cnt) {
    int ka = s_k[wrp][v], ia = s_i[wrp][v];
    float4 fa = __ldg(&f4[(size_t)ia * 32 + lane]);
    float4 wa = __ldg(&w4[(size_t)ka * 32 + lane]);
    a0 += fa.x * wa.x;
    a1 += fa.y * wa.y;
    a2 += fa.z * wa.z;
    a3 += fa.w * wa.w;
  }

  float s1 = a0 + a1 + a2 + a3;
  float s2 = a0 * a0 + a1 * a1 + a2 * a2 + a3 * a3;
#pragma unroll
  for (int o = 16; o > 0; o >>= 1) {
    s1 += __shfl_xor_sync(0xffffffffu, s1, o);
    s2 += __shfl_xor_sync(0xffffffffu, s2, o);
  }
  float mu = s1 * (1.f / 128.f);
  float var = s2 * (1.f / 128.f) - mu * mu;
  float rstd = rsqrtf(var + 1e-6f);
  float4 gg = ((const float4*)ln_g)[lane];
  float4 gb = ((const float4*)ln_b)[lane];
  float v0 = (a0 - mu) * rstd * gg.x + gb.x;
  float v1 = (a1 - mu) * rstd * gg.y + gb.y;
  float v2 = (a2 - mu) * rstd * gg.z + gb.z;
  float v3 = (a3 - mu) * rstd * gg.w + gb.w;
  union { __half2 h[2]; uint2 u; } o;
  o.h[0] = __floats2half2_rn(v0, v1);
  o.h[1] = __floats2half2_rn(v2, v3);
  *(uint2*)&g_x[(size_t)site * DIM + lane * 4] = o.u;
}

// w1 [128,512] -> transposed fp16 w1t [n][k]; block 0 zeros g_sumsq
__global__ __launch_bounds__(256) void k_prepw1(const float* __restrict__ w1) {
  if (blockIdx.x == 0) {
    g_sumsq[threadIdx.x] = 0.f;
    g_sumsq[threadIdx.x + 256] = 0.f;
  }
  int i = blockIdx.x * 256 + threadIdx.x;  // 0..65535
  int n = i >> 7, k = i & 127;
  g_w1t[i] = __float2half_rn(w1[k * HID + n]);
}

// ---------------------------------------------------------------------------
// GEMM1: h = GELU(x @ w1 + b1)  (+ per-channel sumsq for GRN)
// 3128 CTAs (M x N tiles); monolithic K=128; fragment-space epilogue.
// ---------------------------------------------------------------------------
__global__ __launch_bounds__(256, 2) void k_gemm1(const float* __restrict__ b1) {
  extern __shared__ char smem[];
  __shared__ float s_ss[128];
  uint32_t sb = smem_u32(smem);
  int tid = threadIdx.x, lane = tid & 31, w = tid >> 5;
  int wm = w & 1, wn = w >> 1;
  int m0 = blockIdx.x * 128, n0 = blockIdx.y * 128;
  if (tid < 128) s_ss[tid] = 0.f;

#pragma unroll
  for (int i = 0; i < 8; i++) {
    int g = i * 256 + tid;
    int r = g >> 4, c16 = g & 15;
    uint32_t dst = sb + ((uint32_t)(c16 >> 3) << 14) + r * 128 + (((c16 & 7) ^ (r & 7)) << 4);
    int gr = m0 + r;
    uint32_t sz = (gr < N_SITES) ? 16u : 0u;
    int grc = (gr < N_SITES) ? gr : 0;
    cpa16(dst, g_x + (size_t)grc * DIM + c16 * 8, sz);
  }
#pragma unroll
  for (int i = 0; i < 8; i++) {
    int g = i * 256 + tid;
    int r = g >> 4, c16 = g & 15;
    uint32_t dst = sb + G1_OFF_B + ((uint32_t)(c16 >> 3) << 14) + r * 128 +
                   (((c16 & 7) ^ (r & 7)) << 4);
    cpa16(dst, g_w1t + (size_t)(n0 + r) * DIM + c16 * 8, 16);
  }
  CP_COMMIT();

  uint32_t abase[4], axor[4], bbase[2], bxor[2];
  {
    int ar = wm * 64 + (lane & 15);
#pragma unroll
    for (int mt = 0; mt < 4; mt++) {
      int r = ar + mt * 16;
      abase[mt] = r * 128;
      axor[mt] = (r & 7) << 4;
    }
    int br = wn * 32 + ((lane >> 4) << 3) + (lane & 7);
#pragma unroll
    for (int np = 0; np < 2; np++) {
      int r = br + np * 16;
      bbase[np] = G1_OFF_B + r * 128;
      bxor[np] = (r & 7) << 4;
    }
  }
  uint32_t acs = lane >> 4, bcs = (lane >> 3) & 1;

  CP_WAIT0();
  __syncthreads();

  float acc[4][4][4] = {};
#pragma unroll
  for (int ks = 0; ks < 8; ks++) {
    uint32_t ho = (uint32_t)(ks >> 2) << 14;
    uint32_t ksl = ks & 3;
    uint32_t a[4][4], b[2][4];
#pragma unroll
    for (int np = 0; np < 2; np++)
      ldsm4(b[np], sb + bbase[np] + ho + ((((ksl * 2 + bcs) << 4)) ^ bxor[np]));
#pragma unroll
    for (int mt = 0; mt < 4; mt++)
      ldsm4(a[mt], sb + abase[mt] + ho + ((((ksl * 2 + acs) << 4)) ^ axor[mt]));
#pragma unroll
    for (int mt = 0; mt < 4; mt++)
#pragma unroll
      for (int nt = 0; nt < 4; nt++)
        mma16816(acc[mt][nt], a[mt], &b[nt >> 1][(nt & 1) * 2]);
  }
  __syncthreads();

  // ---- fragment-space epilogue: bias + fast GELU + sumsq, stmatrix stage ---
  float2 b_r[4];
#pragma unroll
  for (int nt = 0; nt < 4; nt++)
    b_r[nt] = *(const float2*)&b1[n0 + wn * 32 + nt * 8 + (lane & 3) * 2];

  float ss[8] = {0, 0, 0, 0, 0, 0, 0, 0};
  uint32_t st_base = sb + (uint32_t)(wm * 64 + (lane & 7)) * STG_HB +
                     (uint32_t)(wn * 32 + ((lane >> 3) << 3)) * 2;
#pragma unroll
  for (int mt = 0; mt < 4; mt++) {
    int r0 = m0 + wm * 64 + mt * 16 + (lane >> 2);
    float ok0 = (r0 < N_SITES) ? 1.f : 0.f;
    float ok1 = (r0 + 8 < N_SITES) ? 1.f : 0.f;
    uint32_t p01[4], p23[4];
#pragma unroll
    for (int nt = 0; nt < 4; nt++) {
      float x0 = acc[mt][nt][0] + b_r[nt].x;
      float x1 = acc[mt][nt][1] + b_r[nt].y;
      float x2 = acc[mt][nt][2] + b_r[nt].x;
      float x3 = acc[mt][nt][3] + b_r[nt].y;
      float g0 = ok0 * gelu_fast(x0);
      float g1 = ok0 * gelu_fast(x1);
      float g2 = ok1 * gelu_fast(x2);
      float g3 = ok1 * gelu_fast(x3);
      ss[nt * 2] += g0 * g0 + g2 * g2;
      ss[nt * 2 + 1] += g1 * g1 + g3 * g3;
      union { __half2 h; uint32_t u; } u01, u23;
      u01.h = __floats2half2_rn(g0, g1);
      u23.h = __floats2half2_rn(g2, g3);
      p01[nt] = u01.u;
      p23[nt] = u23.u;
    }
    uint32_t a0 = st_base + (uint32_t)(mt * 16) * STG_HB;
    stsm4(a0, p01[0], p01[1], p01[2], p01[3]);
    stsm4(a0 + 8 * STG_HB, p23[0], p23[1], p23[2], p23[3]);
  }
#pragma unroll
  for (int e = 0; e < 8; e++) {
    ss[e] += __shfl_xor_sync(0xffffffffu, ss[e], 4);
    ss[e] += __shfl_xor_sync(0xffffffffu, ss[e], 8);
    ss[e] += __shfl_xor_sync(0xffffffffu, ss[e], 16);
  }
  if (lane < 4) {
#pragma unroll
    for (int nt = 0; nt < 4; nt++) {
      atomicAdd(&s_ss[wn * 32 + nt * 8 + (lane & 3) * 2], ss[nt * 2]);
      atomicAdd(&s_ss[wn * 32 + nt * 8 + (lane & 3) * 2 + 1], ss[nt * 2 + 1]);
    }
  }
  __syncthreads();

  uint32_t ci = (tid & 15) * 16;
#pragma unroll
  for (int p = 0; p < 8; p++) {
    int rr = p * 16 + (tid >> 4);
    int m = m0 + rr;
    if (m < N_SITES) {
      uint4 v = *(uint4*)(smem + rr * STG_HB + ci);
      *(uint4*)&g_h[(size_t)m * HID + n0 + (tid & 15) * 8] = v;
    }
  }
  if (tid < 128) atomicAdd(&g_sumsq[n0 + tid], s_ss[tid]);
}

// ---------------------------------------------------------------------------
// Fold (with inline GRN): scale[k] = grn_g[k]*nx[k]+1;
// w2s[n][k] = scale[k]*w2[k][n]; bias2[n] = b2[n] + grn_b @ w2
// ---------------------------------------------------------------------------
__global__ __launch_bounds__(128) void k_fold(const float* __restrict__ grn_g,
                                              const float* __restrict__ grn_b,
                                              const float* __restrict__ w2,
                                              const float* __restrict__ b2) {
  int n = blockIdx.x;
  int t = threadIdx.x;
  float gx[4];
  float loc = 0.f;
#pragma unroll
  for (int j = 0; j < 4; j++) {
    gx[j] = sqrtf(g_sumsq[t + j * 128]);
    loc += gx[j];
  }
  __shared__ float red[4];
#pragma unroll
  for (int o = 16; o > 0; o >>= 1) loc += __shfl_xor_sync(0xffffffffu, loc, o);
  if ((t & 31) == 0) red[t >> 5] = loc;
  __syncthreads();
  float mean = (red[0] + red[1] + red[2] + red[3]) * (1.f / 512.f);
  float inv = 1.f / (mean + 1e-6f);

  float part = 0.f;
#pragma unroll
  for (int j = 0; j < 4; j++) {
    int kk = t + j * 128;
    float wv = w2[kk * DIM + n];
    part += grn_b[kk] * wv;
    float scale = grn_g[kk] * (gx[j] * inv) + 1.f;
    g_w2s[n * HID + kk] = __float2half_rn(scale * wv);
  }
#pragma unroll
  for (int o = 16; o > 0; o >>= 1) part += __shfl_xor_sync(0xffffffffu, part, o);
  if ((t & 31) == 0) red[t >> 5] = part;
  __syncthreads();
  if (t == 0) g_bias2[n] = b2[n] + red[0] + red[1] + red[2] + red[3];
}

// ---------------------------------------------------------------------------
// GEMM2: out = (h .* scale) @ w2 + bias2 + feats
// K=512 in 8 chunks of 64, 3-stage cp.async pipeline; fragment-direct epilogue.
// ---------------------------------------------------------------------------
__global__ __launch_bounds__(256, 2) void k_gemm2(const float* __restrict__ feats,
                                                  float* __restrict__ out) {
  extern __shared__ char smem[];
  uint32_t sb = smem_u32(smem);
  int tid = threadIdx.x, lane = tid & 31, w = tid >> 5;
  int wm = w & 1, wn = w >> 1;
  int m0 = blockIdx.x * 128;

  uint32_t abase[4], axor[4], bbase[2], bxor[2];
  {
    int ar = wm * 64 + (lane & 15);
#pragma unroll
    for (int mt = 0; mt < 4; mt++) {
      int r = ar + mt * 16;
      abase[mt] = r * 128;
      axor[mt] = (r & 7) << 4;
    }
    int br = wn * 32 + ((lane >> 4) << 3) + (lane & 7);
#pragma unroll
    for (int np = 0; np < 2; np++) {
      int r = br + np * 16;
      bbase[np] = G2_OFF_B + r * 128;
      bxor[np] = (r & 7) << 4;
    }
  }
  uint32_t acs = lane >> 4, bcs = (lane >> 3) & 1;

  int lr = tid >> 3, lc = tid & 7;

  float acc[4][4][4] = {};
  const int CH = HID / 64;  // 8

#pragma unroll
  for (int c = 0; c < 2; c++) {
    uint32_t ssb = sb + c * G2_STAGE;
    int k0 = c * 64;
#pragma unroll
    for (int i = 0; i < 4; i++) {
      int r = lr + i * 32;
      int gr = m0 + r;
      uint32_t sz = (gr < N_SITES) ? 16u : 0u;
      int grc = (gr < N_SITES) ? gr : 0;
      cpa16(ssb + r * 128 + (((lc ^ (r & 7))) << 4), g_h + (size_t)grc * HID + k0 + lc * 8, sz);
      cpa16(ssb + G2_OFF_B + r * 128 + (((lc ^ (r & 7))) << 4),
            g_w2s + (size_t)r * HID + k0 + lc * 8, 16);
    }
    CP_COMMIT();
  }
#pragma unroll 1
  for (int c = 0; c < CH; c++) {
    CP_WAIT1();
    __syncthreads();
    uint32_t ssb = sb + (c % 3) * G2_STAGE;
#pragma unroll
    for (int ks = 0; ks < 4; ks++) {
      uint32_t a[4][4], b[2][4];
#pragma unroll
      for (int np = 0; np < 2; np++)
        ldsm4(b[np], ssb + bbase[np] + ((((ks * 2 + bcs) << 4)) ^ bxor[np]));
#pragma unroll
      for (int mt = 0; mt < 4; mt++)
        ldsm4(a[mt], ssb + abase[mt] + ((((ks * 2 + acs) << 4)) ^ axor[mt]));
#pragma unroll
      for (int mt = 0; mt < 4; mt++)
#pragma unroll
        for (int nt = 0; nt < 4; nt++)
          mma16816(acc[mt][nt], a[mt], &b[nt >> 1][(nt & 1) * 2]);
    }
    int pc = c + 2;
    if (pc < CH) {
      uint32_t psb = sb + (pc % 3) * G2_STAGE;
      int k0 = pc * 64;
#pragma unroll
      for (int i = 0; i < 4; i++) {
        int r = lr + i * 32;
        int gr = m0 + r;
        uint32_t sz = (gr < N_SITES) ? 16u : 0u;
        int grc = (gr < N_SITES) ? gr : 0;
        cpa16(psb + r * 128 + (((lc ^ (r & 7))) << 4), g_h + (size_t)grc * HID + k0 + lc * 8, sz);
        cpa16(psb + G2_OFF_B + r * 128 + (((lc ^ (r & 7))) << 4),
              g_w2s + (size_t)r * HID + k0 + lc * 8, 16);
      }
    }
    CP_COMMIT();
  }

  // ---- fragment-direct epilogue: + bias2 + feats, float2 stores ----
  float2 b_r[4];
#pragma unroll
  for (int nt = 0; nt < 4; nt++)
    b_r[nt] = *(const float2*)&g_bias2[wn * 32 + nt * 8 + (lane & 3) * 2];
#pragma unroll
  for (int mt = 0; mt < 4; mt++) {
    int r0 = m0 + wm * 64 + mt * 16 + (lane >> 2);
#pragma unroll
    for (int nt = 0; nt < 4; nt++) {
      int n = wn * 32 + nt * 8 + (lane & 3) * 2;
      if (r0 < N_SITES) {
        float2 f = *(const float2*)&feats[(size_t)r0 * DIM + n];
        float2 o;
        o.x = acc[mt][nt][0] + b_r[nt].x + f.x;
        o.y = acc[mt][nt][1] + b_r[nt].y + f.y;
        *(float2*)&out[(size_t)r0 * DIM + n] = o;
      }
      if (r0 + 8 < N_SITES) {
        float2 f = *(const float2*)&feats[(size_t)(r0 + 8) * DIM + n];
        float2 o;
        o.x = acc[mt][nt][2] + b_r[nt].x + f.x;
        o.y = acc[mt][nt][3] + b_r[nt].y + f.y;
        *(float2*)&out[(size_t)(r0 + 8) * DIM + n] = o;
      }
    }
  }
}

// ---------------------------------------------------------------------------
extern "C" void kernel_launch(void* const* d_in, const int* in_sizes, int n_in,
                              void* d_out, int out_size) {
  const float* feats = (const float*)d_in[0];
  const int* nidx = (const int*)d_in[1];
  const float* dw_w = (const float*)d_in[2];
  const float* dw_b = (const float*)d_in[3];
  const float* ln_g = (const float*)d_in[4];
  const float* ln_b = (const float*)d_in[5];
  const float* w1 = (const float*)d_in[6];
  const float* b1 = (const float*)d_in[7];
  const float* grn_g = (const float*)d_in[8];
  const float* grn_b = (const float*)d_in[9];
  const float* w2 = (const float*)d_in[10];
  const float* b2 = (const float*)d_in[11];
  float* out = (float*)d_out;

  cudaFuncSetAttribute(k_gemm1, cudaFuncAttributeMaxDynamicSharedMemorySize, G1_SMEM);
  cudaFuncSetAttribute(k_gemm2, cudaFuncAttributeMaxDynamicSharedMemorySize, G2_SMEM);

  const int MT = (N_SITES + 127) / 128;  // 782
  k_prepw1<<<256, 256>>>(w1);
  k_dwln<<<N_SITES / 8, 256>>>(feats, nidx, dw_w, dw_b, ln_g, ln_b);
  k_gemm1<<<dim3(MT, HID / 128), 256, G1_SMEM>>>(b1);
  k_fold<<<DIM, 128>>>(grn_g, grn_b, w2, b2);
  k_gemm2<<<MT, 256, G2_SMEM>>>(feats, out);
}